// round 7
// baseline (speedup 1.0000x reference)
#include <cuda_runtime.h>

// Single-kernel deterministic reduction for 0.5 * sum((d1-d2)^2) via
// FIXED-POINT INTEGER accumulation:
//   - each block computes a float partial, converts to int64 at scale 2^28,
//     atomicAdd's it into a global int64 accumulator. Integer adds are
//     associative -> result is bitwise deterministic for ANY arrival order.
//   - the last block to arrive (int counter) converts the int64 total to
//     float, writes out[0], and resets accumulator+counter for graph replay.
// No second kernel, no partials array, near-zero reduction tail.

#define GRID_BLOCKS 4736
#define BLOCK_THREADS 256
#define FP_SCALE 268435456.0     // 2^28

__device__ unsigned long long g_acc = 0;      // two's-complement int64 sum
__device__ unsigned int g_counter = 0;

__global__ void __launch_bounds__(BLOCK_THREADS)
mse_fused_kernel(const float4* __restrict__ a,
                 const float4* __restrict__ b,
                 int n4,
                 const float* __restrict__ a_s,
                 const float* __restrict__ b_s,
                 int n,
                 float* __restrict__ out)
{
    float acc = 0.0f;
    const int stride = gridDim.x * blockDim.x;
    int i = blockIdx.x * blockDim.x + threadIdx.x;

    #pragma unroll 4
    for (; i < n4; i += stride) {
        float4 x = __ldcs(a + i);   // streaming: read-once data
        float4 y = __ldcs(b + i);
        float d0 = x.x - y.x;
        float d1 = x.y - y.y;
        float d2 = x.z - y.z;
        float d3 = x.w - y.w;
        acc = fmaf(d0, d0, acc);
        acc = fmaf(d1, d1, acc);
        acc = fmaf(d2, d2, acc);
        acc = fmaf(d3, d3, acc);
    }

    // Scalar tail (n not multiple of 4): block 0, thread 0.
    if (blockIdx.x == 0 && threadIdx.x == 0) {
        for (int t = n4 * 4; t < n; ++t) {
            float d = a_s[t] - b_s[t];
            acc = fmaf(d, d, acc);
        }
    }

    // Block reduce (fixed order within block -> deterministic partial)
    #pragma unroll
    for (int o = 16; o > 0; o >>= 1)
        acc += __shfl_down_sync(0xffffffffu, acc, o);

    __shared__ float smem[BLOCK_THREADS / 32];
    __shared__ bool is_last;
    const int lane = threadIdx.x & 31;
    const int wid  = threadIdx.x >> 5;
    if (lane == 0) smem[wid] = acc;
    __syncthreads();

    if (threadIdx.x == 0) {
        float part = 0.0f;
        #pragma unroll
        for (int w = 0; w < BLOCK_THREADS / 32; ++w)
            part += smem[w];

        // Fixed-point convert (double rounding: exact & deterministic).
        long long q = (long long)llrint((double)part * FP_SCALE);
        atomicAdd(&g_acc, (unsigned long long)q);   // associative -> order-free
        __threadfence();                            // acc visible before count
        unsigned int prev = atomicAdd(&g_counter, 1u);
        is_last = (prev == GRID_BLOCKS - 1);
    }
    __syncthreads();

    if (is_last && threadIdx.x == 0) {
        __threadfence();
        long long total = (long long)g_acc;
        out[0] = (float)(0.5 * ((double)total / FP_SCALE));
        // Reset for next graph replay (no other block is still running).
        g_acc = 0ull;
        __threadfence();
        g_counter = 0;
    }
}

extern "C" void kernel_launch(void* const* d_in, const int* in_sizes, int n_in,
                              void* d_out, int out_size)
{
    const float* d1 = (const float*)d_in[0];
    const float* d2 = (const float*)d_in[1];
    float* out = (float*)d_out;

    const int n  = in_sizes[0];   // 40,000,000
    const int n4 = n >> 2;

    mse_fused_kernel<<<GRID_BLOCKS, BLOCK_THREADS>>>(
        (const float4*)d1, (const float4*)d2, n4, d1, d2, n, out);
}

// round 8
// speedup vs baseline: 1.0351x; 1.0351x over previous
#include <cuda_runtime.h>

// Single-kernel deterministic reduction for 0.5 * sum((d1-d2)^2).
// Fixed-point int64 accumulation (associative -> order-independent, bitwise
// deterministic). Epilogue is THREAD0-ONLY: no fence, no post-atomic
// __syncthreads, no is_last broadcast — warps 1..7 retire immediately, so
// block drain/backfill is not serialized on atomic latency.
// Ordering: atom.acq_rel on the counter (release orders the g_acc add before
// it; acquire orders the winner's g_acc read after it).

#define GRID_BLOCKS 1184
#define BLOCK_THREADS 256
#define FP_SCALE 268435456.0     // 2^28

__device__ unsigned long long g_acc = 0;
__device__ unsigned int g_counter = 0;

__global__ void __launch_bounds__(BLOCK_THREADS)
mse_fused_kernel(const float4* __restrict__ a,
                 const float4* __restrict__ b,
                 int n4,
                 const float* __restrict__ a_s,
                 const float* __restrict__ b_s,
                 int n,
                 float* __restrict__ out)
{
    float acc = 0.0f;
    const int stride = gridDim.x * blockDim.x;
    int i = blockIdx.x * blockDim.x + threadIdx.x;

    #pragma unroll 4
    for (; i < n4; i += stride) {
        float4 x = __ldcs(a + i);   // streaming: read-once data
        float4 y = __ldcs(b + i);
        float d0 = x.x - y.x;
        float d1 = x.y - y.y;
        float d2 = x.z - y.z;
        float d3 = x.w - y.w;
        acc = fmaf(d0, d0, acc);
        acc = fmaf(d1, d1, acc);
        acc = fmaf(d2, d2, acc);
        acc = fmaf(d3, d3, acc);
    }

    // Scalar tail (n not multiple of 4): block 0, thread 0 folds it into acc.
    if (blockIdx.x == 0 && threadIdx.x == 0) {
        for (int t = n4 * 4; t < n; ++t) {
            float d = a_s[t] - b_s[t];
            acc = fmaf(d, d, acc);
        }
    }

    // Block reduce (fixed order -> deterministic block partial)
    #pragma unroll
    for (int o = 16; o > 0; o >>= 1)
        acc += __shfl_down_sync(0xffffffffu, acc, o);

    __shared__ float smem[BLOCK_THREADS / 32];
    const int lane = threadIdx.x & 31;
    const int wid  = threadIdx.x >> 5;
    if (lane == 0) smem[wid] = acc;
    __syncthreads();
    // All threads except thread 0 are DONE after this point (no more syncs).

    if (threadIdx.x == 0) {
        float part = 0.0f;
        #pragma unroll
        for (int w = 0; w < BLOCK_THREADS / 32; ++w)
            part += smem[w];

        // Fixed-point convert (exact via double) -> associative int64 add.
        long long q = (long long)llrint((double)part * FP_SCALE);
        atomicAdd(&g_acc, (unsigned long long)q);   // relaxed device atomic

        // acq_rel counter bump: release orders the g_acc add before it;
        // acquire orders the winner's subsequent g_acc read.
        unsigned int prev;
        asm volatile("atom.acq_rel.gpu.global.add.u32 %0, [%1], 1;"
                     : "=r"(prev) : "l"(&g_counter) : "memory");

        if (prev == GRID_BLOCKS - 1) {
            // Last arrival: all 1184 g_acc adds are ordered-before this point.
            unsigned long long tot;
            asm volatile("ld.acquire.gpu.global.u64 %0, [%1];"
                         : "=l"(tot) : "l"(&g_acc) : "memory");
            out[0] = (float)(0.5 * ((double)(long long)tot / FP_SCALE));
            // Reset for next graph replay (kernel boundary publishes these).
            g_acc = 0ull;
            g_counter = 0;
        }
    }
}

extern "C" void kernel_launch(void* const* d_in, const int* in_sizes, int n_in,
                              void* d_out, int out_size)
{
    const float* d1 = (const float*)d_in[0];
    const float* d2 = (const float*)d_in[1];
    float* out = (float*)d_out;

    const int n  = in_sizes[0];   // 40,000,000
    const int n4 = n >> 2;

    mse_fused_kernel<<<GRID_BLOCKS, BLOCK_THREADS>>>(
        (const float4*)d1, (const float4*)d2, n4, d1, d2, n, out);
}

// round 9
// speedup vs baseline: 1.0559x; 1.0201x over previous
#include <cuda_runtime.h>

// Single-kernel deterministic reduction for 0.5 * sum((d1-d2)^2).
// Fixed-point int64 accumulation (associative -> order-free, bitwise
// deterministic). Per-block epilogue is FIRE-AND-FORGET: two no-return RED
// ops (relaxed add to accumulator, release add to counter) -> blocks retire
// with zero atomic-latency stalls. Block 0's thread 0 polls the counter with
// ld.acquire; when all 1184 arrivals are in, it converts and writes out[0],
// then resets state for the next graph replay (stream order publishes it).

#define GRID_BLOCKS 1184
#define BLOCK_THREADS 256
#define FP_SCALE 268435456.0     // 2^28

__device__ unsigned long long g_acc = 0;
__device__ unsigned int g_counter = 0;

__global__ void __launch_bounds__(BLOCK_THREADS)
mse_fused_kernel(const float4* __restrict__ a,
                 const float4* __restrict__ b,
                 int n4,
                 const float* __restrict__ a_s,
                 const float* __restrict__ b_s,
                 int n,
                 float* __restrict__ out)
{
    float acc = 0.0f;
    const int stride = gridDim.x * blockDim.x;
    int i = blockIdx.x * blockDim.x + threadIdx.x;

    #pragma unroll 4
    for (; i < n4; i += stride) {
        float4 x = __ldcs(a + i);   // streaming: read-once data
        float4 y = __ldcs(b + i);
        float d0 = x.x - y.x;
        float d1 = x.y - y.y;
        float d2 = x.z - y.z;
        float d3 = x.w - y.w;
        acc = fmaf(d0, d0, acc);
        acc = fmaf(d1, d1, acc);
        acc = fmaf(d2, d2, acc);
        acc = fmaf(d3, d3, acc);
    }

    // Scalar tail (n not multiple of 4): block 0, thread 0 folds it in.
    if (blockIdx.x == 0 && threadIdx.x == 0) {
        for (int t = n4 * 4; t < n; ++t) {
            float d = a_s[t] - b_s[t];
            acc = fmaf(d, d, acc);
        }
    }

    // Block reduce (fixed order -> deterministic block partial)
    #pragma unroll
    for (int o = 16; o > 0; o >>= 1)
        acc += __shfl_down_sync(0xffffffffu, acc, o);

    __shared__ float smem[BLOCK_THREADS / 32];
    const int lane = threadIdx.x & 31;
    const int wid  = threadIdx.x >> 5;
    if (lane == 0) smem[wid] = acc;
    __syncthreads();
    // Warps 1..7 are done after this point — no further block-wide waits.

    if (threadIdx.x == 0) {
        float part = 0.0f;
        #pragma unroll
        for (int w = 0; w < BLOCK_THREADS / 32; ++w)
            part += smem[w];

        // Fixed-point convert (exact via double) -> associative int64 red.
        unsigned long long q =
            (unsigned long long)(long long)llrint((double)part * FP_SCALE);

        // Fire-and-forget: no return value, no stall, no block-retire delay.
        asm volatile("red.relaxed.gpu.global.add.u64 [%0], %1;"
                     :: "l"(&g_acc), "l"(q) : "memory");
        // Release: orders this block's g_acc red before its counter bump.
        asm volatile("red.release.gpu.global.add.u32 [%0], %1;"
                     :: "l"(&g_counter), "r"(1u) : "memory");

        // Block 0 finalizes: spin until all arrivals (incl. our own) land.
        if (blockIdx.x == 0) {
            unsigned int c;
            do {
                asm volatile("ld.acquire.gpu.global.u32 %0, [%1];"
                             : "=r"(c) : "l"(&g_counter) : "memory");
            } while (c != GRID_BLOCKS);
            // acquire of the 1184th release -> all g_acc adds are visible.
            unsigned long long tot;
            asm volatile("ld.relaxed.gpu.global.u64 %0, [%1];"
                         : "=l"(tot) : "l"(&g_acc) : "memory");
            out[0] = (float)(0.5 * ((double)(long long)tot / FP_SCALE));
            // Reset for next graph replay; kernel boundary publishes these.
            g_acc = 0ull;
            g_counter = 0;
        }
    }
}

extern "C" void kernel_launch(void* const* d_in, const int* in_sizes, int n_in,
                              void* d_out, int out_size)
{
    const float* d1 = (const float*)d_in[0];
    const float* d2 = (const float*)d_in[1];
    float* out = (float*)d_out;

    const int n  = in_sizes[0];   // 40,000,000
    const int n4 = n >> 2;

    mse_fused_kernel<<<GRID_BLOCKS, BLOCK_THREADS>>>(
        (const float4*)d1, (const float4*)d2, n4, d1, d2, n, out);
}